// round 16
// baseline (speedup 1.0000x reference)
#include <cuda_runtime.h>
#include <cuda_bf16.h>
#include <math.h>
#include <stdint.h>

#define NN 10000
#define EE 160000
#define GG 64
#define HH 4
#define EDIM 32
#define NNHH (NN * HH)

// ---------------- static scratch ----------------
// zero-region: [0, 40000) = deg (int), [40000, 680000) = al accumulation slots
__device__ unsigned char g_zmem[680000];
__device__ int   g_rowptr[NN + 1];
__device__ int   g_cursor[NN];
__device__ int   g_eperm[EE];
__device__ __nv_bfloat16 g_yhi[(size_t)NN * 1024];
__device__ __nv_bfloat16 g_ylo[(size_t)NN * 1024];
__device__ float g_hA[(size_t)NN * 256];
__device__ float g_hB[(size_t)NN * 256];
__device__ float g_alsrc[NNHH];
__device__ float g_aldst[NNHH];
__device__ float g_ale[(size_t)EE * 12];     // [e][l*4+h] contiguous 48B per edge
__device__ float g_M[3 * HH * EDIM];          // [l][h][d]
__device__ float g_Was[3 * 1024];             // per-layer [l][k*HH+h]
__device__ float g_Wad[3 * 1024];
__device__ __nv_bfloat16 g_bhi[327680];
__device__ __nv_bfloat16 g_blo[327680];

// ---------------- generic PTX helpers (compute_103-safe) ----------------
__device__ __forceinline__ uint32_t smem_u32(const void* p) {
    uint32_t a;
    asm("{ .reg .u64 t; cvta.to.shared.u64 t, %1; cvt.u32.u64 %0, t; }"
        : "=r"(a) : "l"(p));
    return a;
}
__device__ __forceinline__ void cp_async16(uint32_t saddr, const void* gptr) {
    asm volatile("cp.async.ca.shared.global [%0], [%1], 16;"
                 :: "r"(saddr), "l"(gptr) : "memory");
}
__device__ __forceinline__ void cp_commit() {
    asm volatile("cp.async.commit_group;" ::: "memory");
}
template <int N>
__device__ __forceinline__ void cp_wait() {
    asm volatile("cp.async.wait_group %0;" :: "n"(N) : "memory");
}
__device__ __forceinline__ void ldsm_x4(uint32_t* r, uint32_t addr) {
    asm volatile("ldmatrix.sync.aligned.m8n8.x4.shared.b16 {%0,%1,%2,%3}, [%4];"
                 : "=r"(r[0]), "=r"(r[1]), "=r"(r[2]), "=r"(r[3]) : "r"(addr));
}
__device__ __forceinline__ void mma_bf16(float* d, const uint32_t* a,
                                         uint32_t b0, uint32_t b1) {
    asm volatile(
        "mma.sync.aligned.m16n8k16.row.col.f32.bf16.bf16.f32 "
        "{%0,%1,%2,%3}, {%4,%5,%6,%7}, {%8,%9}, {%0,%1,%2,%3};"
        : "+f"(d[0]), "+f"(d[1]), "+f"(d[2]), "+f"(d[3])
        : "r"(a[0]), "r"(a[1]), "r"(a[2]), "r"(a[3]), "r"(b0), "r"(b1));
}

// ---------------- prefix scan (deg -> rowptr/cursor), single block ----------------
__global__ void __launch_bounds__(1024) k_scan(const int* __restrict__ deg) {
    __shared__ int wsum[32];
    int t = threadIdx.x;
    int lane = t & 31, w = t >> 5;
    int v[10];
    int s = 0;
    int base = t * 10;
    if (t < 1000) {
#pragma unroll
        for (int i = 0; i < 10; i++) { v[i] = deg[base + i]; s += v[i]; }
    }
    int ps = s;
#pragma unroll
    for (int o = 1; o < 32; o <<= 1) {
        int u = __shfl_up_sync(0xffffffffu, ps, o);
        if (lane >= o) ps += u;
    }
    if (lane == 31) wsum[w] = ps;
    __syncthreads();
    if (w == 0) {
        int xv = wsum[lane];
#pragma unroll
        for (int o = 1; o < 32; o <<= 1) {
            int u = __shfl_up_sync(0xffffffffu, xv, o);
            if (lane >= o) xv += u;
        }
        wsum[lane] = xv;
    }
    __syncthreads();
    int excl = ps - s + (w > 0 ? wsum[w - 1] : 0);
    if (t == 0) g_rowptr[0] = 0;
    if (t < 1000) {
        int run = excl;
#pragma unroll
        for (int i = 0; i < 10; i++) {
            g_cursor[base + i] = run;
            run += v[i];
            g_rowptr[base + i + 1] = run;
        }
    }
}

// ---------------- region helpers ----------------
__device__ void prep_region(int b, const float* __restrict__ W,
                            const float* __restrict__ We,
                            const float* __restrict__ a_s,
                            const float* __restrict__ a_d,
                            const float* __restrict__ a_e,
                            int KD, int C, int wa_blocks, int layer) {
    int lane = threadIdx.x & 31;
    int wrp = threadIdx.x >> 5;
    if (b < wa_blocks) {
        int idx = b * 8 + wrp;
        if (idx < KD * HH) {
            int k = idx / HH, h = idx % HH;
            const float* wrow = W + (size_t)k * HH * C + h * C;
            const float* as = a_s + h * C;
            const float* ad = a_d + h * C;
            float s = 0.f, d = 0.f;
            for (int c = lane; c < C; c += 32) {
                float w = wrow[c];
                s += w * as[c];
                d += w * ad[c];
            }
#pragma unroll
            for (int o = 16; o; o >>= 1) {
                s += __shfl_xor_sync(0xffffffffu, s, o);
                d += __shfl_xor_sync(0xffffffffu, d, o);
            }
            if (lane == 0) {
                g_Was[layer * 1024 + k * HH + h] = s;
                g_Wad[layer * 1024 + k * HH + h] = d;
            }
        }
    } else {
        int idx = (b - wa_blocks) * 8 + wrp;
        if (idx < EDIM * HH) {
            int d = idx / HH, h = idx % HH;
            const float* werow = We + (size_t)d * HH * C + h * C;
            const float* ae = a_e + h * C;
            float s = 0.f;
            for (int c = lane; c < C; c += 32) s += werow[c] * ae[c];
#pragma unroll
            for (int o = 16; o; o >>= 1) s += __shfl_xor_sync(0xffffffffu, s, o);
            if (lane == 0) g_M[layer * (HH * EDIM) + h * EDIM + d] = s;
        }
    }
}

__device__ void trans_region(int tile, const float* __restrict__ W, int KD, int CD,
                             __nv_bfloat16* __restrict__ bhi,
                             __nv_bfloat16* __restrict__ blo, float* sbuf /*32*33*/) {
    int KG = HH * KD;
    int ntx = KG / 32;
    int kg0 = (tile % ntx) * 32;
    int n0 = (tile / ntx) * 32;
    int tx = threadIdx.x & 31, ty = threadIdx.x >> 5;
#pragma unroll
    for (int i = 0; i < 4; i++) {
        int kg = kg0 + ty * 4 + i;
        int k = kg % KD, h = kg / KD;
        sbuf[(ty * 4 + i) * 33 + tx] = W[(size_t)k * (HH * CD) + h * CD + n0 + tx] * 0.25f;
    }
    __syncthreads();
#pragma unroll
    for (int i = 0; i < 4; i++) {
        int r = ty * 4 + i;
        float v = sbuf[tx * 33 + r];
        __nv_bfloat16 hi = __float2bfloat16(v);
        float rem = v - __bfloat162float(hi);
        size_t o = (size_t)(n0 + r) * KG + kg0 + tx;
        bhi[o] = hi;
        blo[o] = __float2bfloat16(rem);
    }
}

// fused: degree histogram + all-layer prep + all-layer weight transpose/split
__global__ void __launch_bounds__(256) k_big(
    const int* __restrict__ dst, int* __restrict__ deg,
    const float* __restrict__ W0, const float* __restrict__ We0,
    const float* __restrict__ As0, const float* __restrict__ Ad0,
    const float* __restrict__ Ae0,
    const float* __restrict__ W1, const float* __restrict__ We1,
    const float* __restrict__ As1, const float* __restrict__ Ad1,
    const float* __restrict__ Ae1,
    const float* __restrict__ W2, const float* __restrict__ We2,
    const float* __restrict__ As2, const float* __restrict__ Ad2,
    const float* __restrict__ Ae2,
    __nv_bfloat16* __restrict__ bhi, __nv_bfloat16* __restrict__ blo) {
    __shared__ float sbuf[32 * 33];
    int b = blockIdx.x;
    if (b < 625) {
        int e = b * 256 + threadIdx.x;
        if (e < EE) atomicAdd(&deg[dst[e]], 1);
    } else if (b < 705) {
        prep_region(b - 625, W0, We0, As0, Ad0, Ae0, 128, 128, 64, 0);
    } else if (b < 785) {
        prep_region(b - 705, W1, We1, As1, Ad1, Ae1, 128, 256, 64, 1);
    } else if (b < 929) {
        prep_region(b - 785, W2, We2, As2, Ad2, Ae2, 256, 128, 128, 2);
    } else if (b < 993) {
        trans_region(b - 929, W0, 128, 128, bhi, blo, sbuf);
    } else if (b < 1121) {
        trans_region(b - 993, W1, 128, 256, bhi + 65536, blo + 65536, sbuf);
    } else {
        trans_region(b - 1121, W2, 256, 128, bhi + 196608, blo + 196608, sbuf);
    }
}

// ---------------- al / ale regions ----------------
__device__ __forceinline__ void al_region(const float* __restrict__ x,
                                          const float* __restrict__ Was_g,
                                          const float* __restrict__ Wad_g,
                                          int KD, float4* Was4, float4* Wad4,
                                          int nblk) {
    int tid = threadIdx.x;
    const float4* wg = (const float4*)Was_g;
    const float4* dg = (const float4*)Wad_g;
    for (int i = tid; i < KD; i += 256) { Was4[i] = wg[i]; Wad4[i] = dg[i]; }
    __syncthreads();
    int lane = tid & 31;
    int n = nblk * 8 + (tid >> 5);
    if (n >= NN) return;
    float s[HH] = {0, 0, 0, 0}, d[HH] = {0, 0, 0, 0};
    const float* xrow = x + (size_t)n * KD;
    for (int k = lane; k < KD; k += 32) {
        float xv = xrow[k];
        float4 ws = Was4[k], wd = Wad4[k];
        s[0] += xv * ws.x; s[1] += xv * ws.y; s[2] += xv * ws.z; s[3] += xv * ws.w;
        d[0] += xv * wd.x; d[1] += xv * wd.y; d[2] += xv * wd.z; d[3] += xv * wd.w;
    }
#pragma unroll
    for (int h = 0; h < HH; h++)
#pragma unroll
        for (int o = 16; o; o >>= 1) {
            s[h] += __shfl_xor_sync(0xffffffffu, s[h], o);
            d[h] += __shfl_xor_sync(0xffffffffu, d[h], o);
        }
    if (lane == 0) {
        *(float4*)(g_alsrc + n * HH) = make_float4(s[0], s[1], s[2], s[3]);
        *(float4*)(g_aldst + n * HH) = make_float4(d[0], d[1], d[2], d[3]);
    }
}

// 4 lanes per edge, writes [e][12] contiguous
__device__ __forceinline__ void ale_region(int eb, const float* __restrict__ eattr,
                                           float4* Ms4) {
    int tid = threadIdx.x;
    if (tid < 96) {
        int lh = tid >> 3, q = tid & 7;
        Ms4[lh * 8 + q] = *(const float4*)(g_M + lh * EDIM + q * 4);
    }
    __syncthreads();
    int e = eb + (tid >> 2);
    int q = tid & 3;
    if (e >= EE) return;
    const float4* p = (const float4*)(eattr + (size_t)e * EDIM);
    float4 v0 = p[q];
    float4 v1 = p[q + 4];
    float a[12];
#pragma unroll
    for (int lh = 0; lh < 12; lh++) {
        float4 m0 = Ms4[lh * 8 + q];
        float4 m1 = Ms4[lh * 8 + q + 4];
        a[lh] = v0.x * m0.x + v0.y * m0.y + v0.z * m0.z + v0.w * m0.w
              + v1.x * m1.x + v1.y * m1.y + v1.z * m1.z + v1.w * m1.w;
    }
#pragma unroll
    for (int o = 1; o <= 2; o <<= 1)
#pragma unroll
        for (int lh = 0; lh < 12; lh++)
            a[lh] += __shfl_xor_sync(0xffffffffu, a[lh], o);
    if (q == 0) {
        float* base = g_ale + (size_t)e * 12;
#pragma unroll
        for (int l = 0; l < 3; l++)
            *(float4*)(base + l * 4)
                = make_float4(a[l * 4 + 0], a[l * 4 + 1], a[l * 4 + 2], a[l * 4 + 3]);
    }
}

// fused: CSR scatter + al layer0 + ale (all layers)
__global__ void __launch_bounds__(256) k_alale(const int* __restrict__ dst,
                                               const float* __restrict__ x,
                                               const float* __restrict__ Was_g,
                                               const float* __restrict__ Wad_g,
                                               const float* __restrict__ eattr) {
    __shared__ float4 sb[512];
    int b = blockIdx.x;
    if (b < 625) {
        int e = b * 256 + threadIdx.x;
        if (e < EE) {
            int p = atomicAdd(&g_cursor[dst[e]], 1);
            g_eperm[p] = e;
        }
    } else if (b < 1875) {
        al_region(x, Was_g, Wad_g, 128, sb, sb + 256, b - 625);
    } else {
        ale_region((b - 1875) * 64, eattr, sb);
    }
}

// ---------------- fused softmax + aggregation: WARP PER NODE ----------------
__device__ __forceinline__ float lrelu(float v) { return v >= 0.f ? v : 0.2f * v; }

template <int KD>
__global__ void __launch_bounds__(256) k_fsa(const int* __restrict__ src,
                                             const float* __restrict__ x,
                                             const float* __restrict__ ale,
                                             const float* __restrict__ alsrc,
                                             const float* __restrict__ aldst,
                                             __nv_bfloat16* __restrict__ yhi,
                                             __nv_bfloat16* __restrict__ ylo) {
    constexpr int R = KD / 128;
    constexpr int KG = HH * KD;
    __shared__ float4 swgt[8][32];
    __shared__ int    ssrc[8][32];

    int tid = threadIdx.x, lane = tid & 31, w = tid >> 5;
    int n = blockIdx.x * 8 + w;
    if (n >= NN) return;
    int st = g_rowptr[n], en = g_rowptr[n + 1];
    int deg = en - st;
    bool small = (deg <= 32);

    float4 ad4 = *(const float4*)(aldst + n * HH);
    float4 an4 = *(const float4*)(alsrc + n * HH);

    float mx0 = -1e30f, mx1 = -1e30f, mx2 = -1e30f, mx3 = -1e30f;
    float sa0 = 0.f, sa1 = 0.f, sa2 = 0.f, sa3 = 0.f;
    float rl0 = 0.f, rl1 = 0.f, rl2 = 0.f, rl3 = 0.f;
    int   rsv = 0;

    if (small) {
        if (lane < deg) {
            int e = g_eperm[st + lane];
            rsv = src[e];
            float4 al4 = *(const float4*)(ale + (size_t)e * 12);
            float4 as4 = *(const float4*)(alsrc + (size_t)rsv * HH);
            sa0 = al4.x; sa1 = al4.y; sa2 = al4.z; sa3 = al4.w;
            rl0 = lrelu(as4.x + ad4.x + al4.x);
            rl1 = lrelu(as4.y + ad4.y + al4.y);
            rl2 = lrelu(as4.z + ad4.z + al4.z);
            rl3 = lrelu(as4.w + ad4.w + al4.w);
            mx0 = rl0; mx1 = rl1; mx2 = rl2; mx3 = rl3;
        }
    } else {
        for (int j = lane; j < deg; j += 32) {
            int e = g_eperm[st + j];
            int s = src[e];
            float4 al4 = *(const float4*)(ale + (size_t)e * 12);
            float4 as4 = *(const float4*)(alsrc + (size_t)s * HH);
            sa0 += al4.x; sa1 += al4.y; sa2 += al4.z; sa3 += al4.w;
            mx0 = fmaxf(mx0, lrelu(as4.x + ad4.x + al4.x));
            mx1 = fmaxf(mx1, lrelu(as4.y + ad4.y + al4.y));
            mx2 = fmaxf(mx2, lrelu(as4.z + ad4.z + al4.z));
            mx3 = fmaxf(mx3, lrelu(as4.w + ad4.w + al4.w));
        }
    }
#pragma unroll
    for (int o = 16; o; o >>= 1) {
        mx0 = fmaxf(mx0, __shfl_xor_sync(0xffffffffu, mx0, o));
        mx1 = fmaxf(mx1, __shfl_xor_sync(0xffffffffu, mx1, o));
        mx2 = fmaxf(mx2, __shfl_xor_sync(0xffffffffu, mx2, o));
        mx3 = fmaxf(mx3, __shfl_xor_sync(0xffffffffu, mx3, o));
        sa0 += __shfl_xor_sync(0xffffffffu, sa0, o);
        sa1 += __shfl_xor_sync(0xffffffffu, sa1, o);
        sa2 += __shfl_xor_sync(0xffffffffu, sa2, o);
        sa3 += __shfl_xor_sync(0xffffffffu, sa3, o);
    }
    float inv = 1.f / (float)(deg > 0 ? deg : 1);
    float ll0 = lrelu(an4.x + ad4.x + sa0 * inv);
    float ll1 = lrelu(an4.y + ad4.y + sa1 * inv);
    float ll2 = lrelu(an4.z + ad4.z + sa2 * inv);
    float ll3 = lrelu(an4.w + ad4.w + sa3 * inv);
    mx0 = fmaxf(mx0, ll0); mx1 = fmaxf(mx1, ll1);
    mx2 = fmaxf(mx2, ll2); mx3 = fmaxf(mx3, ll3);
    float lw0 = expf(ll0 - mx0), lw1 = expf(ll1 - mx1);
    float lw2 = expf(ll2 - mx2), lw3 = expf(ll3 - mx3);

    float ws0 = 0.f, ws1 = 0.f, ws2 = 0.f, ws3 = 0.f;
    float4 acc[R][HH];
#pragma unroll
    for (int r = 0; r < R; r++)
#pragma unroll
        for (int h = 0; h < HH; h++) acc[r][h] = make_float4(0.f, 0.f, 0.f, 0.f);

    if (small) {
        float w0v = 0.f, w1v = 0.f, w2v = 0.f, w3v = 0.f;
        if (lane < deg) {
            w0v = expf(rl0 - mx0);
            w1v = expf(rl1 - mx1);
            w2v = expf(rl2 - mx2);
            w3v = expf(rl3 - mx3);
            ws0 = w0v; ws1 = w1v; ws2 = w2v; ws3 = w3v;
        }
        ssrc[w][lane] = rsv;
        swgt[w][lane] = make_float4(w0v, w1v, w2v, w3v);
        __syncwarp();
#pragma unroll 2
        for (int jj = 0; jj < deg; jj++) {
            int s = ssrc[w][jj];
            float4 wj = swgt[w][jj];
            const float4* xr = (const float4*)(x + (size_t)s * KD);
#pragma unroll
            for (int r = 0; r < R; r++) {
                float4 xv = xr[r * 32 + lane];
                acc[r][0].x += wj.x * xv.x; acc[r][0].y += wj.x * xv.y;
                acc[r][0].z += wj.x * xv.z; acc[r][0].w += wj.x * xv.w;
                acc[r][1].x += wj.y * xv.x; acc[r][1].y += wj.y * xv.y;
                acc[r][1].z += wj.y * xv.z; acc[r][1].w += wj.y * xv.w;
                acc[r][2].x += wj.z * xv.x; acc[r][2].y += wj.z * xv.y;
                acc[r][2].z += wj.z * xv.z; acc[r][2].w += wj.z * xv.w;
                acc[r][3].x += wj.w * xv.x; acc[r][3].y += wj.w * xv.y;
                acc[r][3].z += wj.w * xv.z; acc[r][3].w += wj.w * xv.w;
            }
        }
        __syncwarp();
    } else {
        for (int j0 = 0; j0 < deg; j0 += 32) {
            int j = j0 + lane;
            float w0v = 0.f, w1v = 0.f, w2v = 0.f, w3v = 0.f;
            int sv = 0;
            if (j < deg) {
                int e = g_eperm[st + j];
                sv = src[e];
                float4 al4 = *(const float4*)(ale + (size_t)e * 12);
                float4 as4 = *(const float4*)(alsrc + (size_t)sv * HH);
                w0v = expf(lrelu(as4.x + ad4.x + al4.x) - mx0);
                w1v = expf(lrelu(as4.y + ad4.y + al4.y) - mx1);
                w2v = expf(lrelu(as4.z + ad4.z + al4.z) - mx2);
                w3v = expf(lrelu(as4.w + ad4.w + al4.w) - mx3);
                ws0 += w0v; ws1 += w1v; ws2 += w2v; ws3 += w3v;
            }
            ssrc[w][lane] = sv;
            swgt[w][lane] = make_float4(w0v, w1v, w2v, w3v);
            __syncwarp();
            int cnt = deg - j0;
            if (cnt > 32) cnt = 32;
#pragma unroll 2
            for (int jj = 0; jj < cnt; jj++) {
                int s = ssrc[w][jj];
                float4 wj = swgt[w][jj];
                const float4* xr = (const float4*)(x + (size_t)s * KD);
#pragma unroll
                for (int r = 0; r < R; r++) {
                    float4 xv = xr[r * 32 + lane];
                    acc[r][0].x += wj.x * xv.x; acc[r][0].y += wj.x * xv.y;
                    acc[r][0].z += wj.x * xv.z; acc[r][0].w += wj.x * xv.w;
                    acc[r][1].x += wj.y * xv.x; acc[r][1].y += wj.y * xv.y;
                    acc[r][1].z += wj.y * xv.z; acc[r][1].w += wj.y * xv.w;
                    acc[r][2].x += wj.z * xv.x; acc[r][2].y += wj.z * xv.y;
                    acc[r][2].z += wj.z * xv.z; acc[r][2].w += wj.z * xv.w;
                    acc[r][3].x += wj.w * xv.x; acc[r][3].y += wj.w * xv.y;
                    acc[r][3].z += wj.w * xv.z; acc[r][3].w += wj.w * xv.w;
                }
            }
            __syncwarp();
        }
    }
#pragma unroll
    for (int o = 16; o; o >>= 1) {
        ws0 += __shfl_xor_sync(0xffffffffu, ws0, o);
        ws1 += __shfl_xor_sync(0xffffffffu, ws1, o);
        ws2 += __shfl_xor_sync(0xffffffffu, ws2, o);
        ws3 += __shfl_xor_sync(0xffffffffu, ws3, o);
    }
    float is0 = 1.f / (ws0 + lw0 + 1e-16f);
    float is1 = 1.f / (ws1 + lw1 + 1e-16f);
    float is2 = 1.f / (ws2 + lw2 + 1e-16f);
    float is3 = 1.f / (ws3 + lw3 + 1e-16f);

    {
        const float4* xr = (const float4*)(x + (size_t)n * KD);
#pragma unroll
        for (int r = 0; r < R; r++) {
            float4 xv = xr[r * 32 + lane];
            acc[r][0].x += lw0 * xv.x; acc[r][0].y += lw0 * xv.y;
            acc[r][0].z += lw0 * xv.z; acc[r][0].w += lw0 * xv.w;
            acc[r][1].x += lw1 * xv.x; acc[r][1].y += lw1 * xv.y;
            acc[r][1].z += lw1 * xv.z; acc[r][1].w += lw1 * xv.w;
            acc[r][2].x += lw2 * xv.x; acc[r][2].y += lw2 * xv.y;
            acc[r][2].z += lw2 * xv.z; acc[r][2].w += lw2 * xv.w;
            acc[r][3].x += lw3 * xv.x; acc[r][3].y += lw3 * xv.y;
            acc[r][3].z += lw3 * xv.z; acc[r][3].w += lw3 * xv.w;
        }
    }
    float isv[HH] = {is0, is1, is2, is3};
#pragma unroll
    for (int r = 0; r < R; r++) {
#pragma unroll
        for (int h = 0; h < HH; h++) {
            float4 v = acc[r][h];
            v.x *= isv[h]; v.y *= isv[h]; v.z *= isv[h]; v.w *= isv[h];
            __nv_bfloat16 h0 = __float2bfloat16(v.x);
            __nv_bfloat16 h1 = __float2bfloat16(v.y);
            __nv_bfloat16 h2 = __float2bfloat16(v.z);
            __nv_bfloat16 h3 = __float2bfloat16(v.w);
            __nv_bfloat16 l0 = __float2bfloat16(v.x - __bfloat162float(h0));
            __nv_bfloat16 l1 = __float2bfloat16(v.y - __bfloat162float(h1));
            __nv_bfloat16 l2 = __float2bfloat16(v.z - __bfloat162float(h2));
            __nv_bfloat16 l3 = __float2bfloat16(v.w - __bfloat162float(h3));
            size_t o = (size_t)n * KG + h * KD + (r * 32 + lane) * 4;
            ushort4 ho = make_ushort4(*(unsigned short*)&h0, *(unsigned short*)&h1,
                                      *(unsigned short*)&h2, *(unsigned short*)&h3);
            ushort4 lo = make_ushort4(*(unsigned short*)&l0, *(unsigned short*)&l1,
                                      *(unsigned short*)&l2, *(unsigned short*)&l3);
            *(ushort4*)(yhi + o) = ho;
            *(ushort4*)(ylo + o) = lo;
        }
    }
}

// ---------------- warp-MMA bf16 split GEMM + fused next-layer al epilogue ----------------
// BM=32, BN=128, BK=32; 256 threads = 8 warps (2 x 4); warp tile 16x32.
// Grid x = 313 (2+ CTAs/SM) fixes the occupancy ceiling measured at BM=64.
template <int KG, int CD>
__global__ void __launch_bounds__(256) k_hgemm(const __nv_bfloat16* __restrict__ yhi,
                                               const __nv_bfloat16* __restrict__ ylo,
                                               const __nv_bfloat16* __restrict__ bhi,
                                               const __nv_bfloat16* __restrict__ blo,
                                               const float* __restrict__ bias,
                                               float* __restrict__ hout,
                                               const float* __restrict__ wa_s_next,
                                               const float* __restrict__ wa_d_next,
                                               float* __restrict__ aout_s,
                                               float* __restrict__ aout_d) {
    constexpr int NC = KG / 32;
    constexpr int A_HI = 0;
    constexpr int A_LO = 2560;      // 32*80
    constexpr int B_HI = 5120;
    constexpr int B_LO = 15360;     // B_HI + 128*80
    constexpr int STAGE = 25600;
    extern __shared__ char smem[];
    __shared__ float4 sWas[128];
    __shared__ float4 sWad[128];

    int tid = threadIdx.x;
    int lane = tid & 31, wid = tid >> 5;
    int warp_m = wid >> 2;          // 0..1 -> 16 rows each
    int warp_n = wid & 3;           // 0..3 -> 32 cols each
    int m0 = blockIdx.x * 32;
    int n0 = blockIdx.y * 128;
    uint32_t sbase0 = smem_u32(smem);
    bool fuse_al = (wa_s_next != nullptr);

    if (fuse_al) {
        const float4* ws = (const float4*)wa_s_next;
        const float4* wd = (const float4*)wa_d_next;
        for (int i = tid; i < 128; i += 256) {
            sWas[i] = ws[n0 + i];
            sWad[i] = wd[n0 + i];
        }
    }

    float acc[4][4];
#pragma unroll
    for (int j = 0; j < 4; j++)
#pragma unroll
        for (int k = 0; k < 4; k++) acc[j][k] = 0.f;

    auto load_stage = [&](int kc, int buf) {
        uint32_t sb = sbase0 + buf * STAGE;
        int kg0 = kc * 32;
        // A: 256 16B chunks (hi 128, lo 128), 1 per thread
        {
            int half = tid >> 7;
            int rem = tid & 127;
            int r = rem >> 2, ch = rem & 3;
            int row = m0 + r;
            if (row >= NN) row = NN - 1;
            const __nv_bfloat16* gp = (half ? ylo : yhi) + (size_t)row * KG + kg0 + ch * 8;
            cp_async16(sb + (half ? A_LO : A_HI) + r * 80 + ch * 16, gp);
        }
        // B: 1024 16B chunks (hi 512, lo 512), 4 per thread
#pragma unroll
        for (int i = 0; i < 4; i++) {
            int idx = i * 256 + tid;
            int half = idx >> 9;
            int rem = idx & 511;
            int r = rem >> 2, ch = rem & 3;
            const __nv_bfloat16* gp = (half ? blo : bhi) + (size_t)(n0 + r) * KG + kg0 + ch * 8;
            cp_async16(sb + (half ? B_LO : B_HI) + r * 80 + ch * 16, gp);
        }
        cp_commit();
    };

    load_stage(0, 0);

    for (int kc = 0; kc < NC; kc++) {
        int buf = kc & 1;
        if (kc + 1 < NC) { load_stage(kc + 1, buf ^ 1); cp_wait<1>(); }
        else             { cp_wait<0>(); }
        __syncthreads();

        uint32_t sb = sbase0 + buf * STAGE;
#pragma unroll
        for (int k16 = 0; k16 < 2; k16++) {
            uint32_t ah[4], al_[4];
            {
                int row = warp_m * 16 + (lane & 7) + ((lane >> 3) & 1) * 8;
                int chunk = lane >> 4;
                uint32_t addr = sb + A_HI + row * 80 + k16 * 32 + chunk * 16;
                ldsm_x4(ah, addr);
                ldsm_x4(al_, addr + (A_LO - A_HI));
            }
            uint32_t bh[2][4], bl[2][4];
#pragma unroll
            for (int g = 0; g < 2; g++) {
                int row = warp_n * 32 + g * 16 + (lane & 7) + ((lane >> 4) & 1) * 8;
                int chunk = (lane >> 3) & 1;
                uint32_t addr = sb + B_HI + row * 80 + k16 * 32 + chunk * 16;
                ldsm_x4(bh[g], addr);
                ldsm_x4(bl[g], addr + (B_LO - B_HI));
            }
#pragma unroll
            for (int na = 0; na < 4; na++) {
                int g = na >> 1, s = (na & 1) * 2;
                mma_bf16(acc[na], ah, bh[g][s], bh[g][s + 1]);
                mma_bf16(acc[na], ah, bl[g][s], bl[g][s + 1]);
                mma_bf16(acc[na], al_, bh[g][s], bh[g][s + 1]);
            }
        }
        __syncthreads();
    }

    // ---- epilogue: bias + ELU + store + fused next-layer al accumulation ----
    float sAcc[2][4], dAcc[2][4];
#pragma unroll
    for (int m = 0; m < 2; m++)
#pragma unroll
        for (int h = 0; h < 4; h++) { sAcc[m][h] = 0.f; dAcc[m][h] = 0.f; }

    int row = m0 + warp_m * 16 + (lane >> 2);
#pragma unroll
    for (int na = 0; na < 4; na++) {
        int cl = warp_n * 32 + na * 8 + (lane & 3) * 2;
        int col = n0 + cl;
        float b0 = bias[col], b1 = bias[col + 1];
        float v0 = acc[na][0] + b0;
        float v1 = acc[na][1] + b1;
        float v2 = acc[na][2] + b0;
        float v3 = acc[na][3] + b1;
        float o0 = v0 > 0.f ? v0 : expm1f(v0);
        float o1 = v1 > 0.f ? v1 : expm1f(v1);
        float o2 = v2 > 0.f ? v2 : expm1f(v2);
        float o3 = v3 > 0.f ? v3 : expm1f(v3);
        if (row < NN)
            *(float2*)(hout + (size_t)row * CD + col) = make_float2(o0, o1);
        if (row + 8 < NN)
            *(float2*)(hout + (size_t)(row + 8) * CD + col) = make_float2(o2, o3);
        if (fuse_al) {
            float4 ws0 = sWas[cl], ws1 = sWas[cl + 1];
            float4 wd0 = sWad[cl], wd1 = sWad[cl + 1];
            sAcc[0][0] += o0 * ws0.x + o1 * ws1.x;
            sAcc[0][1] += o0 * ws0.y + o1 * ws1.y;
            sAcc[0][2] += o0 * ws0.z + o1 * ws1.z;
            sAcc[0][3] += o0 * ws0.w + o1 * ws1.w;
            dAcc[0][0] += o0 * wd0.x + o1 * wd1.x;
            dAcc[0][1] += o0 * wd0.y + o1 * wd1.y;
            dAcc[0][2] += o0 * wd0.z + o1 * wd1.z;
            dAcc[0][3] += o0 * wd0.w + o1 * wd1.w;
            sAcc[1][0] += o2 * ws0.x + o3 * ws1.x;
            sAcc[1][1] += o2 * ws0.y + o3 * ws1.y;
            sAcc[1][2] += o2 * ws0.z + o3 * ws1.z;
            sAcc[1][3] += o2 * ws0.w + o3 * ws1.w;
            dAcc[1][0] += o2 * wd0.x + o3 * wd1.x;
            dAcc[1][1] += o2 * wd0.y + o3 * wd1.y;
            dAcc[1][2] += o2 * wd0.z + o3 * wd1.z;
            dAcc[1][3] += o2 * wd0.w + o3 * wd1.w;
        }
    }
    if (fuse_al) {
#pragma unroll
        for (int o = 1; o <= 2; o <<= 1) {
#pragma unroll
            for (int m = 0; m < 2; m++)
#pragma unroll
                for (int h = 0; h < 4; h++) {
                    sAcc[m][h] += __shfl_xor_sync(0xffffffffu, sAcc[m][h], o);
                    dAcc[m][h] += __shfl_xor_sync(0xffffffffu, dAcc[m][h], o);
                }
        }
        if ((lane & 3) == 0) {
#pragma unroll
            for (int m = 0; m < 2; m++) {
                int rr = row + m * 8;
                if (rr < NN) {
#pragma unroll
                    for (int h = 0; h < 4; h++) {
                        atomicAdd(&aout_s[rr * HH + h], sAcc[m][h]);
                        atomicAdd(&aout_d[rr * HH + h], dAcc[m][h]);
                    }
                }
            }
        }
    }
}

// ---------------- graph mean pooling ----------------
__global__ void k_pool2(const int* __restrict__ batch, const float* __restrict__ h,
                        float* __restrict__ out) {
    int g = blockIdx.x;
    int t = threadIdx.x;
    int lo = 0, hiB = NN;
    while (lo < hiB) { int m = (lo + hiB) >> 1; if (batch[m] < g) lo = m + 1; else hiB = m; }
    int lo2 = lo, hi2 = NN;
    while (lo2 < hi2) { int m = (lo2 + hi2) >> 1; if (batch[m] < g + 1) lo2 = m + 1; else hi2 = m; }
    int cnt = lo2 - lo;
    float acc = 0.f;
    int n = lo;
    for (; n + 4 <= lo2; n += 4) {
        float a0 = h[(size_t)(n + 0) * 128 + t];
        float a1 = h[(size_t)(n + 1) * 128 + t];
        float a2 = h[(size_t)(n + 2) * 128 + t];
        float a3 = h[(size_t)(n + 3) * 128 + t];
        acc += (a0 + a1) + (a2 + a3);
    }
    for (; n < lo2; n++) acc += h[(size_t)n * 128 + t];
    out[(size_t)g * 128 + t] = acc / (float)(cnt > 0 ? cnt : 1);
}

// ---------------- launch ----------------
extern "C" void kernel_launch(void* const* d_in, const int* in_sizes, int n_in,
                              void* d_out, int out_size) {
    const float* x     = (const float*)d_in[0];
    const int*   ei    = (const int*)d_in[1];
    const float* eattr = (const float*)d_in[2];
    const int*   batch = (const int*)d_in[3];
    const int* src = ei;
    const int* dst = ei + EE;

    const float* W[3]  = {(const float*)d_in[4],  (const float*)d_in[10], (const float*)d_in[16]};
    const float* We[3] = {(const float*)d_in[5],  (const float*)d_in[11], (const float*)d_in[17]};
    const float* As[3] = {(const float*)d_in[6],  (const float*)d_in[12], (const float*)d_in[18]};
    const float* Ad[3] = {(const float*)d_in[7],  (const float*)d_in[13], (const float*)d_in[19]};
    const float* Ae[3] = {(const float*)d_in[8],  (const float*)d_in[14], (const float*)d_in[20]};
    const float* Bb[3] = {(const float*)d_in[9],  (const float*)d_in[15], (const float*)d_in[21]};
    (void)n_in; (void)in_sizes; (void)out_size;

    float* out = (float*)d_out;

    void *p_zmem, *p_yhi, *p_ylo, *p_hA, *p_hB, *p_bhi, *p_blo, *p_ale, *p_was, *p_wad;
    void *p_alsrc, *p_aldst;
    cudaGetSymbolAddress(&p_zmem, g_zmem);
    cudaGetSymbolAddress(&p_yhi, g_yhi);
    cudaGetSymbolAddress(&p_ylo, g_ylo);
    cudaGetSymbolAddress(&p_hA, g_hA);
    cudaGetSymbolAddress(&p_hB, g_hB);
    cudaGetSymbolAddress(&p_bhi, g_bhi);
    cudaGetSymbolAddress(&p_blo, g_blo);
    cudaGetSymbolAddress(&p_ale, g_ale);
    cudaGetSymbolAddress(&p_was, g_Was);
    cudaGetSymbolAddress(&p_wad, g_Wad);
    cudaGetSymbolAddress(&p_alsrc, g_alsrc);
    cudaGetSymbolAddress(&p_aldst, g_aldst);
    unsigned char* zp = (unsigned char*)p_zmem;
    int*   degp   = (int*)zp;
    float* an     = (float*)(zp + 40000);
    __nv_bfloat16* yhi = (__nv_bfloat16*)p_yhi;
    __nv_bfloat16* ylo = (__nv_bfloat16*)p_ylo;
    float* hA = (float*)p_hA;
    float* hB = (float*)p_hB;
    __nv_bfloat16* bhi = (__nv_bfloat16*)p_bhi;
    __nv_bfloat16* blo = (__nv_bfloat16*)p_blo;
    float* ale = (float*)p_ale;
    float* wasp = (float*)p_was;
    float* wadp = (float*)p_wad;
    float* al0s = (float*)p_alsrc;
    float* al0d = (float*)p_aldst;

    const int SMEM_BYTES = 51200;
    cudaFuncSetAttribute((const void*)k_hgemm<512, 128>,
                         cudaFuncAttributeMaxDynamicSharedMemorySize, SMEM_BYTES);
    cudaFuncSetAttribute((const void*)k_hgemm<512, 256>,
                         cudaFuncAttributeMaxDynamicSharedMemorySize, SMEM_BYTES);
    cudaFuncSetAttribute((const void*)k_hgemm<1024, 128>,
                         cudaFuncAttributeMaxDynamicSharedMemorySize, SMEM_BYTES);

    cudaMemsetAsync(p_zmem, 0, 680000);

    k_big<<<1249, 256>>>(dst, degp,
                         W[0], We[0], As[0], Ad[0], Ae[0],
                         W[1], We[1], As[1], Ad[1], Ae[1],
                         W[2], We[2], As[2], Ad[2], Ae[2],
                         bhi, blo);
    k_scan<<<1, 1024>>>(degp);
    k_alale<<<625 + 1250 + 2500, 256>>>(dst, x, wasp, wadp, eattr);

    const size_t boff[3] = {0, 65536, 196608};
    const int MB = (NN + 31) / 32;   // 313
    const int FB = (NN + 7) / 8;     // 1250

    // layer 0
    k_fsa<128><<<FB, 256>>>(src, x, ale + 0, al0s, al0d, yhi, ylo);
    k_hgemm<512, 128><<<dim3(MB, 1), 256, SMEM_BYTES>>>(
        yhi, ylo, bhi + boff[0], blo + boff[0], Bb[0], hA,
        wasp + 1 * 1024, wadp + 1 * 1024, an + 0 * NNHH, an + 1 * NNHH);
    // layer 1
    k_fsa<128><<<FB, 256>>>(src, hA, ale + 4,
                            an + 0 * NNHH, an + 1 * NNHH, yhi, ylo);
    k_hgemm<512, 256><<<dim3(MB, 2), 256, SMEM_BYTES>>>(
        yhi, ylo, bhi + boff[1], blo + boff[1], Bb[1], hB,
        wasp + 2 * 1024, wadp + 2 * 1024, an + 2 * NNHH, an + 3 * NNHH);
    // layer 2
    k_fsa<256><<<FB, 256>>>(src, hB, ale + 8,
                            an + 2 * NNHH, an + 3 * NNHH, yhi, ylo);
    k_hgemm<1024, 128><<<dim3(MB, 1), 256, SMEM_BYTES>>>(
        yhi, ylo, bhi + boff[2], blo + boff[2], Bb[2], hA,
        nullptr, nullptr, nullptr, nullptr);

    k_pool2<<<GG, 128>>>(batch, hA, out);
}

// round 17
// speedup vs baseline: 1.1344x; 1.1344x over previous
#include <cuda_runtime.h>
#include <cuda_bf16.h>
#include <math.h>
#include <stdint.h>

#define NN 10000
#define EE 160000
#define GG 64
#define HH 4
#define EDIM 32
#define NNHH (NN * HH)

// ---------------- static scratch ----------------
// zero-region: [0, 40000) = deg (int), [40000, 680000) = al accumulation slots
__device__ unsigned char g_zmem[680000];
__device__ int   g_rowptr[NN + 1];
__device__ int   g_cursor[NN];
__device__ int   g_eperm[EE];
__device__ __nv_bfloat16 g_yhi[(size_t)NN * 1024];
__device__ __nv_bfloat16 g_ylo[(size_t)NN * 1024];
__device__ float g_hA[(size_t)NN * 256];
__device__ float g_hB[(size_t)NN * 256];
__device__ float g_alsrc[NNHH];
__device__ float g_aldst[NNHH];
__device__ float g_ale[(size_t)EE * 12];     // [e][l*4+h] contiguous 48B per edge
__device__ float g_M[3 * HH * EDIM];          // [l][h][d]
__device__ float g_Was[3 * 1024];             // per-layer [l][k*HH+h]
__device__ float g_Wad[3 * 1024];
__device__ __nv_bfloat16 g_bhi[327680];
__device__ __nv_bfloat16 g_blo[327680];

// ---------------- generic PTX helpers (compute_103-safe) ----------------
__device__ __forceinline__ uint32_t smem_u32(const void* p) {
    uint32_t a;
    asm("{ .reg .u64 t; cvta.to.shared.u64 t, %1; cvt.u32.u64 %0, t; }"
        : "=r"(a) : "l"(p));
    return a;
}
__device__ __forceinline__ void cp_async16(uint32_t saddr, const void* gptr) {
    asm volatile("cp.async.ca.shared.global [%0], [%1], 16;"
                 :: "r"(saddr), "l"(gptr) : "memory");
}
__device__ __forceinline__ void cp_commit() {
    asm volatile("cp.async.commit_group;" ::: "memory");
}
template <int N>
__device__ __forceinline__ void cp_wait() {
    asm volatile("cp.async.wait_group %0;" :: "n"(N) : "memory");
}
__device__ __forceinline__ void ldsm_x4(uint32_t* r, uint32_t addr) {
    asm volatile("ldmatrix.sync.aligned.m8n8.x4.shared.b16 {%0,%1,%2,%3}, [%4];"
                 : "=r"(r[0]), "=r"(r[1]), "=r"(r[2]), "=r"(r[3]) : "r"(addr));
}
__device__ __forceinline__ void mma_bf16(float* d, const uint32_t* a,
                                         uint32_t b0, uint32_t b1) {
    asm volatile(
        "mma.sync.aligned.m16n8k16.row.col.f32.bf16.bf16.f32 "
        "{%0,%1,%2,%3}, {%4,%5,%6,%7}, {%8,%9}, {%0,%1,%2,%3};"
        : "+f"(d[0]), "+f"(d[1]), "+f"(d[2]), "+f"(d[3])
        : "r"(a[0]), "r"(a[1]), "r"(a[2]), "r"(a[3]), "r"(b0), "r"(b1));
}

// ---------------- prefix scan (deg -> rowptr/cursor), single block ----------------
__global__ void __launch_bounds__(1024) k_scan(const int* __restrict__ deg) {
    __shared__ int wsum[32];
    int t = threadIdx.x;
    int lane = t & 31, w = t >> 5;
    int v[10];
    int s = 0;
    int base = t * 10;
    if (t < 1000) {
#pragma unroll
        for (int i = 0; i < 10; i++) { v[i] = deg[base + i]; s += v[i]; }
    }
    int ps = s;
#pragma unroll
    for (int o = 1; o < 32; o <<= 1) {
        int u = __shfl_up_sync(0xffffffffu, ps, o);
        if (lane >= o) ps += u;
    }
    if (lane == 31) wsum[w] = ps;
    __syncthreads();
    if (w == 0) {
        int xv = wsum[lane];
#pragma unroll
        for (int o = 1; o < 32; o <<= 1) {
            int u = __shfl_up_sync(0xffffffffu, xv, o);
            if (lane >= o) xv += u;
        }
        wsum[lane] = xv;
    }
    __syncthreads();
    int excl = ps - s + (w > 0 ? wsum[w - 1] : 0);
    if (t == 0) g_rowptr[0] = 0;
    if (t < 1000) {
        int run = excl;
#pragma unroll
        for (int i = 0; i < 10; i++) {
            g_cursor[base + i] = run;
            run += v[i];
            g_rowptr[base + i + 1] = run;
        }
    }
}

// ---------------- region helpers ----------------
__device__ void prep_region(int b, const float* __restrict__ W,
                            const float* __restrict__ We,
                            const float* __restrict__ a_s,
                            const float* __restrict__ a_d,
                            const float* __restrict__ a_e,
                            int KD, int C, int wa_blocks, int layer) {
    int lane = threadIdx.x & 31;
    int wrp = threadIdx.x >> 5;
    if (b < wa_blocks) {
        int idx = b * 8 + wrp;
        if (idx < KD * HH) {
            int k = idx / HH, h = idx % HH;
            const float* wrow = W + (size_t)k * HH * C + h * C;
            const float* as = a_s + h * C;
            const float* ad = a_d + h * C;
            float s = 0.f, d = 0.f;
            for (int c = lane; c < C; c += 32) {
                float w = wrow[c];
                s += w * as[c];
                d += w * ad[c];
            }
#pragma unroll
            for (int o = 16; o; o >>= 1) {
                s += __shfl_xor_sync(0xffffffffu, s, o);
                d += __shfl_xor_sync(0xffffffffu, d, o);
            }
            if (lane == 0) {
                g_Was[layer * 1024 + k * HH + h] = s;
                g_Wad[layer * 1024 + k * HH + h] = d;
            }
        }
    } else {
        int idx = (b - wa_blocks) * 8 + wrp;
        if (idx < EDIM * HH) {
            int d = idx / HH, h = idx % HH;
            const float* werow = We + (size_t)d * HH * C + h * C;
            const float* ae = a_e + h * C;
            float s = 0.f;
            for (int c = lane; c < C; c += 32) s += werow[c] * ae[c];
#pragma unroll
            for (int o = 16; o; o >>= 1) s += __shfl_xor_sync(0xffffffffu, s, o);
            if (lane == 0) g_M[layer * (HH * EDIM) + h * EDIM + d] = s;
        }
    }
}

__device__ void trans_region(int tile, const float* __restrict__ W, int KD, int CD,
                             __nv_bfloat16* __restrict__ bhi,
                             __nv_bfloat16* __restrict__ blo, float* sbuf /*32*33*/) {
    int KG = HH * KD;
    int ntx = KG / 32;
    int kg0 = (tile % ntx) * 32;
    int n0 = (tile / ntx) * 32;
    int tx = threadIdx.x & 31, ty = threadIdx.x >> 5;
#pragma unroll
    for (int i = 0; i < 4; i++) {
        int kg = kg0 + ty * 4 + i;
        int k = kg % KD, h = kg / KD;
        sbuf[(ty * 4 + i) * 33 + tx] = W[(size_t)k * (HH * CD) + h * CD + n0 + tx] * 0.25f;
    }
    __syncthreads();
#pragma unroll
    for (int i = 0; i < 4; i++) {
        int r = ty * 4 + i;
        float v = sbuf[tx * 33 + r];
        __nv_bfloat16 hi = __float2bfloat16(v);
        float rem = v - __bfloat162float(hi);
        size_t o = (size_t)(n0 + r) * KG + kg0 + tx;
        bhi[o] = hi;
        blo[o] = __float2bfloat16(rem);
    }
}

// fused: degree histogram + all-layer prep + all-layer weight transpose/split
__global__ void __launch_bounds__(256) k_big(
    const int* __restrict__ dst, int* __restrict__ deg,
    const float* __restrict__ W0, const float* __restrict__ We0,
    const float* __restrict__ As0, const float* __restrict__ Ad0,
    const float* __restrict__ Ae0,
    const float* __restrict__ W1, const float* __restrict__ We1,
    const float* __restrict__ As1, const float* __restrict__ Ad1,
    const float* __restrict__ Ae1,
    const float* __restrict__ W2, const float* __restrict__ We2,
    const float* __restrict__ As2, const float* __restrict__ Ad2,
    const float* __restrict__ Ae2,
    __nv_bfloat16* __restrict__ bhi, __nv_bfloat16* __restrict__ blo) {
    __shared__ float sbuf[32 * 33];
    int b = blockIdx.x;
    if (b < 625) {
        int e = b * 256 + threadIdx.x;
        if (e < EE) atomicAdd(&deg[dst[e]], 1);
    } else if (b < 705) {
        prep_region(b - 625, W0, We0, As0, Ad0, Ae0, 128, 128, 64, 0);
    } else if (b < 785) {
        prep_region(b - 705, W1, We1, As1, Ad1, Ae1, 128, 256, 64, 1);
    } else if (b < 929) {
        prep_region(b - 785, W2, We2, As2, Ad2, Ae2, 256, 128, 128, 2);
    } else if (b < 993) {
        trans_region(b - 929, W0, 128, 128, bhi, blo, sbuf);
    } else if (b < 1121) {
        trans_region(b - 993, W1, 128, 256, bhi + 65536, blo + 65536, sbuf);
    } else {
        trans_region(b - 1121, W2, 256, 128, bhi + 196608, blo + 196608, sbuf);
    }
}

// ---------------- al / ale regions ----------------
__device__ __forceinline__ void al_region(const float* __restrict__ x,
                                          const float* __restrict__ Was_g,
                                          const float* __restrict__ Wad_g,
                                          int KD, float4* Was4, float4* Wad4,
                                          int nblk) {
    int tid = threadIdx.x;
    const float4* wg = (const float4*)Was_g;
    const float4* dg = (const float4*)Wad_g;
    for (int i = tid; i < KD; i += 256) { Was4[i] = wg[i]; Wad4[i] = dg[i]; }
    __syncthreads();
    int lane = tid & 31;
    int n = nblk * 8 + (tid >> 5);
    if (n >= NN) return;
    float s[HH] = {0, 0, 0, 0}, d[HH] = {0, 0, 0, 0};
    const float* xrow = x + (size_t)n * KD;
    for (int k = lane; k < KD; k += 32) {
        float xv = xrow[k];
        float4 ws = Was4[k], wd = Wad4[k];
        s[0] += xv * ws.x; s[1] += xv * ws.y; s[2] += xv * ws.z; s[3] += xv * ws.w;
        d[0] += xv * wd.x; d[1] += xv * wd.y; d[2] += xv * wd.z; d[3] += xv * wd.w;
    }
#pragma unroll
    for (int h = 0; h < HH; h++)
#pragma unroll
        for (int o = 16; o; o >>= 1) {
            s[h] += __shfl_xor_sync(0xffffffffu, s[h], o);
            d[h] += __shfl_xor_sync(0xffffffffu, d[h], o);
        }
    if (lane == 0) {
        *(float4*)(g_alsrc + n * HH) = make_float4(s[0], s[1], s[2], s[3]);
        *(float4*)(g_aldst + n * HH) = make_float4(d[0], d[1], d[2], d[3]);
    }
}

// 4 lanes per edge, writes [e][12] contiguous
__device__ __forceinline__ void ale_region(int eb, const float* __restrict__ eattr,
                                           float4* Ms4) {
    int tid = threadIdx.x;
    if (tid < 96) {
        int lh = tid >> 3, q = tid & 7;
        Ms4[lh * 8 + q] = *(const float4*)(g_M + lh * EDIM + q * 4);
    }
    __syncthreads();
    int e = eb + (tid >> 2);
    int q = tid & 3;
    if (e >= EE) return;
    const float4* p = (const float4*)(eattr + (size_t)e * EDIM);
    float4 v0 = p[q];
    float4 v1 = p[q + 4];
    float a[12];
#pragma unroll
    for (int lh = 0; lh < 12; lh++) {
        float4 m0 = Ms4[lh * 8 + q];
        float4 m1 = Ms4[lh * 8 + q + 4];
        a[lh] = v0.x * m0.x + v0.y * m0.y + v0.z * m0.z + v0.w * m0.w
              + v1.x * m1.x + v1.y * m1.y + v1.z * m1.z + v1.w * m1.w;
    }
#pragma unroll
    for (int o = 1; o <= 2; o <<= 1)
#pragma unroll
        for (int lh = 0; lh < 12; lh++)
            a[lh] += __shfl_xor_sync(0xffffffffu, a[lh], o);
    if (q == 0) {
        float* base = g_ale + (size_t)e * 12;
#pragma unroll
        for (int l = 0; l < 3; l++)
            *(float4*)(base + l * 4)
                = make_float4(a[l * 4 + 0], a[l * 4 + 1], a[l * 4 + 2], a[l * 4 + 3]);
    }
}

// fused: CSR scatter + al layer0 + ale (all layers)
__global__ void __launch_bounds__(256) k_alale(const int* __restrict__ dst,
                                               const float* __restrict__ x,
                                               const float* __restrict__ Was_g,
                                               const float* __restrict__ Wad_g,
                                               const float* __restrict__ eattr) {
    __shared__ float4 sb[512];
    int b = blockIdx.x;
    if (b < 625) {
        int e = b * 256 + threadIdx.x;
        if (e < EE) {
            int p = atomicAdd(&g_cursor[dst[e]], 1);
            g_eperm[p] = e;
        }
    } else if (b < 1875) {
        al_region(x, Was_g, Wad_g, 128, sb, sb + 256, b - 625);
    } else {
        ale_region((b - 1875) * 64, eattr, sb);
    }
}

// ---------------- fused softmax + aggregation: WARP PER NODE ----------------
__device__ __forceinline__ float lrelu(float v) { return v >= 0.f ? v : 0.2f * v; }

template <int KD>
__global__ void __launch_bounds__(256) k_fsa(const int* __restrict__ src,
                                             const float* __restrict__ x,
                                             const float* __restrict__ ale,
                                             const float* __restrict__ alsrc,
                                             const float* __restrict__ aldst,
                                             __nv_bfloat16* __restrict__ yhi,
                                             __nv_bfloat16* __restrict__ ylo) {
    constexpr int R = KD / 128;
    constexpr int KG = HH * KD;
    __shared__ float4 swgt[8][32];
    __shared__ int    ssrc[8][32];

    int tid = threadIdx.x, lane = tid & 31, w = tid >> 5;
    int n = blockIdx.x * 8 + w;
    if (n >= NN) return;
    int st = g_rowptr[n], en = g_rowptr[n + 1];
    int deg = en - st;
    bool small = (deg <= 32);

    float4 ad4 = *(const float4*)(aldst + n * HH);
    float4 an4 = *(const float4*)(alsrc + n * HH);

    float mx0 = -1e30f, mx1 = -1e30f, mx2 = -1e30f, mx3 = -1e30f;
    float sa0 = 0.f, sa1 = 0.f, sa2 = 0.f, sa3 = 0.f;
    float rl0 = 0.f, rl1 = 0.f, rl2 = 0.f, rl3 = 0.f;
    int   rsv = 0;

    if (small) {
        if (lane < deg) {
            int e = g_eperm[st + lane];
            rsv = src[e];
            float4 al4 = *(const float4*)(ale + (size_t)e * 12);
            float4 as4 = *(const float4*)(alsrc + (size_t)rsv * HH);
            sa0 = al4.x; sa1 = al4.y; sa2 = al4.z; sa3 = al4.w;
            rl0 = lrelu(as4.x + ad4.x + al4.x);
            rl1 = lrelu(as4.y + ad4.y + al4.y);
            rl2 = lrelu(as4.z + ad4.z + al4.z);
            rl3 = lrelu(as4.w + ad4.w + al4.w);
            mx0 = rl0; mx1 = rl1; mx2 = rl2; mx3 = rl3;
        }
    } else {
        for (int j = lane; j < deg; j += 32) {
            int e = g_eperm[st + j];
            int s = src[e];
            float4 al4 = *(const float4*)(ale + (size_t)e * 12);
            float4 as4 = *(const float4*)(alsrc + (size_t)s * HH);
            sa0 += al4.x; sa1 += al4.y; sa2 += al4.z; sa3 += al4.w;
            mx0 = fmaxf(mx0, lrelu(as4.x + ad4.x + al4.x));
            mx1 = fmaxf(mx1, lrelu(as4.y + ad4.y + al4.y));
            mx2 = fmaxf(mx2, lrelu(as4.z + ad4.z + al4.z));
            mx3 = fmaxf(mx3, lrelu(as4.w + ad4.w + al4.w));
        }
    }
#pragma unroll
    for (int o = 16; o; o >>= 1) {
        mx0 = fmaxf(mx0, __shfl_xor_sync(0xffffffffu, mx0, o));
        mx1 = fmaxf(mx1, __shfl_xor_sync(0xffffffffu, mx1, o));
        mx2 = fmaxf(mx2, __shfl_xor_sync(0xffffffffu, mx2, o));
        mx3 = fmaxf(mx3, __shfl_xor_sync(0xffffffffu, mx3, o));
        sa0 += __shfl_xor_sync(0xffffffffu, sa0, o);
        sa1 += __shfl_xor_sync(0xffffffffu, sa1, o);
        sa2 += __shfl_xor_sync(0xffffffffu, sa2, o);
        sa3 += __shfl_xor_sync(0xffffffffu, sa3, o);
    }
    float inv = 1.f / (float)(deg > 0 ? deg : 1);
    float ll0 = lrelu(an4.x + ad4.x + sa0 * inv);
    float ll1 = lrelu(an4.y + ad4.y + sa1 * inv);
    float ll2 = lrelu(an4.z + ad4.z + sa2 * inv);
    float ll3 = lrelu(an4.w + ad4.w + sa3 * inv);
    mx0 = fmaxf(mx0, ll0); mx1 = fmaxf(mx1, ll1);
    mx2 = fmaxf(mx2, ll2); mx3 = fmaxf(mx3, ll3);
    float lw0 = expf(ll0 - mx0), lw1 = expf(ll1 - mx1);
    float lw2 = expf(ll2 - mx2), lw3 = expf(ll3 - mx3);

    float ws0 = 0.f, ws1 = 0.f, ws2 = 0.f, ws3 = 0.f;
    float4 acc[R][HH];
#pragma unroll
    for (int r = 0; r < R; r++)
#pragma unroll
        for (int h = 0; h < HH; h++) acc[r][h] = make_float4(0.f, 0.f, 0.f, 0.f);

    if (small) {
        float w0v = 0.f, w1v = 0.f, w2v = 0.f, w3v = 0.f;
        if (lane < deg) {
            w0v = expf(rl0 - mx0);
            w1v = expf(rl1 - mx1);
            w2v = expf(rl2 - mx2);
            w3v = expf(rl3 - mx3);
            ws0 = w0v; ws1 = w1v; ws2 = w2v; ws3 = w3v;
        }
        ssrc[w][lane] = rsv;
        swgt[w][lane] = make_float4(w0v, w1v, w2v, w3v);
        __syncwarp();
#pragma unroll 2
        for (int jj = 0; jj < deg; jj++) {
            int s = ssrc[w][jj];
            float4 wj = swgt[w][jj];
            const float4* xr = (const float4*)(x + (size_t)s * KD);
#pragma unroll
            for (int r = 0; r < R; r++) {
                float4 xv = xr[r * 32 + lane];
                acc[r][0].x += wj.x * xv.x; acc[r][0].y += wj.x * xv.y;
                acc[r][0].z += wj.x * xv.z; acc[r][0].w += wj.x * xv.w;
                acc[r][1].x += wj.y * xv.x; acc[r][1].y += wj.y * xv.y;
                acc[r][1].z += wj.y * xv.z; acc[r][1].w += wj.y * xv.w;
                acc[r][2].x += wj.z * xv.x; acc[r][2].y += wj.z * xv.y;
                acc[r][2].z += wj.z * xv.z; acc[r][2].w += wj.z * xv.w;
                acc[r][3].x += wj.w * xv.x; acc[r][3].y += wj.w * xv.y;
                acc[r][3].z += wj.w * xv.z; acc[r][3].w += wj.w * xv.w;
            }
        }
        __syncwarp();
    } else {
        for (int j0 = 0; j0 < deg; j0 += 32) {
            int j = j0 + lane;
            float w0v = 0.f, w1v = 0.f, w2v = 0.f, w3v = 0.f;
            int sv = 0;
            if (j < deg) {
                int e = g_eperm[st + j];
                sv = src[e];
                float4 al4 = *(const float4*)(ale + (size_t)e * 12);
                float4 as4 = *(const float4*)(alsrc + (size_t)sv * HH);
                w0v = expf(lrelu(as4.x + ad4.x + al4.x) - mx0);
                w1v = expf(lrelu(as4.y + ad4.y + al4.y) - mx1);
                w2v = expf(lrelu(as4.z + ad4.z + al4.z) - mx2);
                w3v = expf(lrelu(as4.w + ad4.w + al4.w) - mx3);
                ws0 += w0v; ws1 += w1v; ws2 += w2v; ws3 += w3v;
            }
            ssrc[w][lane] = sv;
            swgt[w][lane] = make_float4(w0v, w1v, w2v, w3v);
            __syncwarp();
            int cnt = deg - j0;
            if (cnt > 32) cnt = 32;
#pragma unroll 2
            for (int jj = 0; jj < cnt; jj++) {
                int s = ssrc[w][jj];
                float4 wj = swgt[w][jj];
                const float4* xr = (const float4*)(x + (size_t)s * KD);
#pragma unroll
                for (int r = 0; r < R; r++) {
                    float4 xv = xr[r * 32 + lane];
                    acc[r][0].x += wj.x * xv.x; acc[r][0].y += wj.x * xv.y;
                    acc[r][0].z += wj.x * xv.z; acc[r][0].w += wj.x * xv.w;
                    acc[r][1].x += wj.y * xv.x; acc[r][1].y += wj.y * xv.y;
                    acc[r][1].z += wj.y * xv.z; acc[r][1].w += wj.y * xv.w;
                    acc[r][2].x += wj.z * xv.x; acc[r][2].y += wj.z * xv.y;
                    acc[r][2].z += wj.z * xv.z; acc[r][2].w += wj.z * xv.w;
                    acc[r][3].x += wj.w * xv.x; acc[r][3].y += wj.w * xv.y;
                    acc[r][3].z += wj.w * xv.z; acc[r][3].w += wj.w * xv.w;
                }
            }
            __syncwarp();
        }
    }
#pragma unroll
    for (int o = 16; o; o >>= 1) {
        ws0 += __shfl_xor_sync(0xffffffffu, ws0, o);
        ws1 += __shfl_xor_sync(0xffffffffu, ws1, o);
        ws2 += __shfl_xor_sync(0xffffffffu, ws2, o);
        ws3 += __shfl_xor_sync(0xffffffffu, ws3, o);
    }
    float is0 = 1.f / (ws0 + lw0 + 1e-16f);
    float is1 = 1.f / (ws1 + lw1 + 1e-16f);
    float is2 = 1.f / (ws2 + lw2 + 1e-16f);
    float is3 = 1.f / (ws3 + lw3 + 1e-16f);

    {
        const float4* xr = (const float4*)(x + (size_t)n * KD);
#pragma unroll
        for (int r = 0; r < R; r++) {
            float4 xv = xr[r * 32 + lane];
            acc[r][0].x += lw0 * xv.x; acc[r][0].y += lw0 * xv.y;
            acc[r][0].z += lw0 * xv.z; acc[r][0].w += lw0 * xv.w;
            acc[r][1].x += lw1 * xv.x; acc[r][1].y += lw1 * xv.y;
            acc[r][1].z += lw1 * xv.z; acc[r][1].w += lw1 * xv.w;
            acc[r][2].x += lw2 * xv.x; acc[r][2].y += lw2 * xv.y;
            acc[r][2].z += lw2 * xv.z; acc[r][2].w += lw2 * xv.w;
            acc[r][3].x += lw3 * xv.x; acc[r][3].y += lw3 * xv.y;
            acc[r][3].z += lw3 * xv.z; acc[r][3].w += lw3 * xv.w;
        }
    }
    float isv[HH] = {is0, is1, is2, is3};
#pragma unroll
    for (int r = 0; r < R; r++) {
#pragma unroll
        for (int h = 0; h < HH; h++) {
            float4 v = acc[r][h];
            v.x *= isv[h]; v.y *= isv[h]; v.z *= isv[h]; v.w *= isv[h];
            __nv_bfloat16 h0 = __float2bfloat16(v.x);
            __nv_bfloat16 h1 = __float2bfloat16(v.y);
            __nv_bfloat16 h2 = __float2bfloat16(v.z);
            __nv_bfloat16 h3 = __float2bfloat16(v.w);
            __nv_bfloat16 l0 = __float2bfloat16(v.x - __bfloat162float(h0));
            __nv_bfloat16 l1 = __float2bfloat16(v.y - __bfloat162float(h1));
            __nv_bfloat16 l2 = __float2bfloat16(v.z - __bfloat162float(h2));
            __nv_bfloat16 l3 = __float2bfloat16(v.w - __bfloat162float(h3));
            size_t o = (size_t)n * KG + h * KD + (r * 32 + lane) * 4;
            ushort4 ho = make_ushort4(*(unsigned short*)&h0, *(unsigned short*)&h1,
                                      *(unsigned short*)&h2, *(unsigned short*)&h3);
            ushort4 lo = make_ushort4(*(unsigned short*)&l0, *(unsigned short*)&l1,
                                      *(unsigned short*)&l2, *(unsigned short*)&l3);
            *(ushort4*)(yhi + o) = ho;
            *(ushort4*)(ylo + o) = lo;
        }
    }
}

// ---------------- warp-MMA bf16 split GEMM + fused next-layer al epilogue ----------------
// BM=64, BN=64, BK=32; 256 threads = 8 warps (2 x 4); warp tile 32x16.
// Grid (157, CD/64) -> 314/628 CTAs: fixes the 1-CTA/SM occupancy ceiling.
template <int KG, int CD>
__global__ void __launch_bounds__(256) k_hgemm(const __nv_bfloat16* __restrict__ yhi,
                                               const __nv_bfloat16* __restrict__ ylo,
                                               const __nv_bfloat16* __restrict__ bhi,
                                               const __nv_bfloat16* __restrict__ blo,
                                               const float* __restrict__ bias,
                                               float* __restrict__ hout,
                                               const float* __restrict__ wa_s_next,
                                               const float* __restrict__ wa_d_next,
                                               float* __restrict__ aout_s,
                                               float* __restrict__ aout_d) {
    constexpr int NC = KG / 32;
    constexpr int A_HI = 0;
    constexpr int A_LO = 5120;      // 64*80
    constexpr int B_HI = 10240;
    constexpr int B_LO = 15360;     // B_HI + 64*80
    constexpr int STAGE = 20480;
    extern __shared__ char smem[];
    __shared__ float4 sWas[64];
    __shared__ float4 sWad[64];

    int tid = threadIdx.x;
    int lane = tid & 31, wid = tid >> 5;
    int warp_m = wid >> 2;          // 0..1 -> 32 rows each
    int warp_n = wid & 3;           // 0..3 -> 16 cols each
    int m0 = blockIdx.x * 64;
    int n0 = blockIdx.y * 64;
    uint32_t sbase0 = smem_u32(smem);
    bool fuse_al = (wa_s_next != nullptr);

    if (fuse_al) {
        const float4* ws = (const float4*)wa_s_next;
        const float4* wd = (const float4*)wa_d_next;
        if (tid < 64) {
            sWas[tid] = ws[n0 + tid];
            sWad[tid] = wd[n0 + tid];
        }
    }

    float acc[2][2][4];
#pragma unroll
    for (int i = 0; i < 2; i++)
#pragma unroll
        for (int j = 0; j < 2; j++)
#pragma unroll
            for (int k = 0; k < 4; k++) acc[i][j][k] = 0.f;

    auto load_stage = [&](int kc, int buf) {
        uint32_t sb = sbase0 + buf * STAGE;
        int kg0 = kc * 32;
        // A: 512 16B chunks (hi 256, lo 256), 2 per thread
#pragma unroll
        for (int i = 0; i < 2; i++) {
            int idx = i * 256 + tid;
            int half = idx >> 8;
            int rem = idx & 255;
            int r = rem >> 2, ch = rem & 3;
            int row = m0 + r;
            if (row >= NN) row = NN - 1;
            const __nv_bfloat16* gp = (half ? ylo : yhi) + (size_t)row * KG + kg0 + ch * 8;
            cp_async16(sb + (half ? A_LO : A_HI) + r * 80 + ch * 16, gp);
        }
        // B: 512 16B chunks (hi 256, lo 256), 2 per thread
#pragma unroll
        for (int i = 0; i < 2; i++) {
            int idx = i * 256 + tid;
            int half = idx >> 8;
            int rem = idx & 255;
            int r = rem >> 2, ch = rem & 3;
            const __nv_bfloat16* gp = (half ? blo : bhi) + (size_t)(n0 + r) * KG + kg0 + ch * 8;
            cp_async16(sb + (half ? B_LO : B_HI) + r * 80 + ch * 16, gp);
        }
        cp_commit();
    };

    load_stage(0, 0);

    for (int kc = 0; kc < NC; kc++) {
        int buf = kc & 1;
        if (kc + 1 < NC) { load_stage(kc + 1, buf ^ 1); cp_wait<1>(); }
        else             { cp_wait<0>(); }
        __syncthreads();

        uint32_t sb = sbase0 + buf * STAGE;
#pragma unroll
        for (int k16 = 0; k16 < 2; k16++) {
            uint32_t ah[2][4], al_[2][4];
#pragma unroll
            for (int ma = 0; ma < 2; ma++) {
                int row = warp_m * 32 + ma * 16 + (lane & 7) + ((lane >> 3) & 1) * 8;
                int chunk = lane >> 4;
                uint32_t addr = sb + A_HI + row * 80 + k16 * 32 + chunk * 16;
                ldsm_x4(ah[ma], addr);
                ldsm_x4(al_[ma], addr + (A_LO - A_HI));
            }
            uint32_t bh[4], bl[4];
            {
                int row = warp_n * 16 + (lane & 7) + ((lane >> 4) & 1) * 8;
                int chunk = (lane >> 3) & 1;
                uint32_t addr = sb + B_HI + row * 80 + k16 * 32 + chunk * 16;
                ldsm_x4(bh, addr);
                ldsm_x4(bl, addr + (B_LO - B_HI));
            }
#pragma unroll
            for (int ma = 0; ma < 2; ma++)
#pragma unroll
                for (int na = 0; na < 2; na++) {
                    int s = na * 2;
                    mma_bf16(acc[ma][na], ah[ma], bh[s], bh[s + 1]);
                    mma_bf16(acc[ma][na], ah[ma], bl[s], bl[s + 1]);
                    mma_bf16(acc[ma][na], al_[ma], bh[s], bh[s + 1]);
                }
        }
        __syncthreads();
    }

    // ---- epilogue: bias + ELU + store + fused next-layer al accumulation ----
    float sAcc[4][4], dAcc[4][4];
#pragma unroll
    for (int m = 0; m < 4; m++)
#pragma unroll
        for (int h = 0; h < 4; h++) { sAcc[m][h] = 0.f; dAcc[m][h] = 0.f; }

#pragma unroll
    for (int ma = 0; ma < 2; ma++) {
        int row = m0 + warp_m * 32 + ma * 16 + (lane >> 2);
#pragma unroll
        for (int na = 0; na < 2; na++) {
            int cl = warp_n * 16 + na * 8 + (lane & 3) * 2;
            int col = n0 + cl;
            float b0 = bias[col], b1 = bias[col + 1];
            float v0 = acc[ma][na][0] + b0;
            float v1 = acc[ma][na][1] + b1;
            float v2 = acc[ma][na][2] + b0;
            float v3 = acc[ma][na][3] + b1;
            float o0 = v0 > 0.f ? v0 : expm1f(v0);
            float o1 = v1 > 0.f ? v1 : expm1f(v1);
            float o2 = v2 > 0.f ? v2 : expm1f(v2);
            float o3 = v3 > 0.f ? v3 : expm1f(v3);
            if (row < NN)
                *(float2*)(hout + (size_t)row * CD + col) = make_float2(o0, o1);
            if (row + 8 < NN)
                *(float2*)(hout + (size_t)(row + 8) * CD + col) = make_float2(o2, o3);
            if (fuse_al) {
                float4 ws0 = sWas[cl], ws1 = sWas[cl + 1];
                float4 wd0 = sWad[cl], wd1 = sWad[cl + 1];
                int mi = ma * 2;
                sAcc[mi][0] += o0 * ws0.x + o1 * ws1.x;
                sAcc[mi][1] += o0 * ws0.y + o1 * ws1.y;
                sAcc[mi][2] += o0 * ws0.z + o1 * ws1.z;
                sAcc[mi][3] += o0 * ws0.w + o1 * ws1.w;
                dAcc[mi][0] += o0 * wd0.x + o1 * wd1.x;
                dAcc[mi][1] += o0 * wd0.y + o1 * wd1.y;
                dAcc[mi][2] += o0 * wd0.z + o1 * wd1.z;
                dAcc[mi][3] += o0 * wd0.w + o1 * wd1.w;
                sAcc[mi + 1][0] += o2 * ws0.x + o3 * ws1.x;
                sAcc[mi + 1][1] += o2 * ws0.y + o3 * ws1.y;
                sAcc[mi + 1][2] += o2 * ws0.z + o3 * ws1.z;
                sAcc[mi + 1][3] += o2 * ws0.w + o3 * ws1.w;
                dAcc[mi + 1][0] += o2 * wd0.x + o3 * wd1.x;
                dAcc[mi + 1][1] += o2 * wd0.y + o3 * wd1.y;
                dAcc[mi + 1][2] += o2 * wd0.z + o3 * wd1.z;
                dAcc[mi + 1][3] += o2 * wd0.w + o3 * wd1.w;
            }
        }
    }
    if (fuse_al) {
#pragma unroll
        for (int o = 1; o <= 2; o <<= 1) {
#pragma unroll
            for (int m = 0; m < 4; m++)
#pragma unroll
                for (int h = 0; h < 4; h++) {
                    sAcc[m][h] += __shfl_xor_sync(0xffffffffu, sAcc[m][h], o);
                    dAcc[m][h] += __shfl_xor_sync(0xffffffffu, dAcc[m][h], o);
                }
        }
        if ((lane & 3) == 0) {
#pragma unroll
            for (int m = 0; m < 4; m++) {
                int ma = m >> 1;
                int row = m0 + warp_m * 32 + ma * 16 + (lane >> 2) + (m & 1) * 8;
                if (row < NN) {
#pragma unroll
                    for (int h = 0; h < 4; h++) {
                        atomicAdd(&aout_s[row * HH + h], sAcc[m][h]);
                        atomicAdd(&aout_d[row * HH + h], dAcc[m][h]);
                    }
                }
            }
        }
    }
}

// ---------------- graph mean pooling ----------------
__global__ void k_pool2(const int* __restrict__ batch, const float* __restrict__ h,
                        float* __restrict__ out) {
    int g = blockIdx.x;
    int t = threadIdx.x;
    int lo = 0, hiB = NN;
    while (lo < hiB) { int m = (lo + hiB) >> 1; if (batch[m] < g) lo = m + 1; else hiB = m; }
    int lo2 = lo, hi2 = NN;
    while (lo2 < hi2) { int m = (lo2 + hi2) >> 1; if (batch[m] < g + 1) lo2 = m + 1; else hi2 = m; }
    int cnt = lo2 - lo;
    float acc = 0.f;
    int n = lo;
    for (; n + 4 <= lo2; n += 4) {
        float a0 = h[(size_t)(n + 0) * 128 + t];
        float a1 = h[(size_t)(n + 1) * 128 + t];
        float a2 = h[(size_t)(n + 2) * 128 + t];
        float a3 = h[(size_t)(n + 3) * 128 + t];
        acc += (a0 + a1) + (a2 + a3);
    }
    for (; n < lo2; n++) acc += h[(size_t)n * 128 + t];
    out[(size_t)g * 128 + t] = acc / (float)(cnt > 0 ? cnt : 1);
}

// ---------------- launch ----------------
extern "C" void kernel_launch(void* const* d_in, const int* in_sizes, int n_in,
                              void* d_out, int out_size) {
    const float* x     = (const float*)d_in[0];
    const int*   ei    = (const int*)d_in[1];
    const float* eattr = (const float*)d_in[2];
    const int*   batch = (const int*)d_in[3];
    const int* src = ei;
    const int* dst = ei + EE;

    const float* W[3]  = {(const float*)d_in[4],  (const float*)d_in[10], (const float*)d_in[16]};
    const float* We[3] = {(const float*)d_in[5],  (const float*)d_in[11], (const float*)d_in[17]};
    const float* As[3] = {(const float*)d_in[6],  (const float*)d_in[12], (const float*)d_in[18]};
    const float* Ad[3] = {(const float*)d_in[7],  (const float*)d_in[13], (const float*)d_in[19]};
    const float* Ae[3] = {(const float*)d_in[8],  (const float*)d_in[14], (const float*)d_in[20]};
    const float* Bb[3] = {(const float*)d_in[9],  (const float*)d_in[15], (const float*)d_in[21]};
    (void)n_in; (void)in_sizes; (void)out_size;

    float* out = (float*)d_out;

    void *p_zmem, *p_yhi, *p_ylo, *p_hA, *p_hB, *p_bhi, *p_blo, *p_ale, *p_was, *p_wad;
    void *p_alsrc, *p_aldst;
    cudaGetSymbolAddress(&p_zmem, g_zmem);
    cudaGetSymbolAddress(&p_yhi, g_yhi);
    cudaGetSymbolAddress(&p_ylo, g_ylo);
    cudaGetSymbolAddress(&p_hA, g_hA);
    cudaGetSymbolAddress(&p_hB, g_hB);
    cudaGetSymbolAddress(&p_bhi, g_bhi);
    cudaGetSymbolAddress(&p_blo, g_blo);
    cudaGetSymbolAddress(&p_ale, g_ale);
    cudaGetSymbolAddress(&p_was, g_Was);
    cudaGetSymbolAddress(&p_wad, g_Wad);
    cudaGetSymbolAddress(&p_alsrc, g_alsrc);
    cudaGetSymbolAddress(&p_aldst, g_aldst);
    unsigned char* zp = (unsigned char*)p_zmem;
    int*   degp   = (int*)zp;
    float* an     = (float*)(zp + 40000);
    __nv_bfloat16* yhi = (__nv_bfloat16*)p_yhi;
    __nv_bfloat16* ylo = (__nv_bfloat16*)p_ylo;
    float* hA = (float*)p_hA;
    float* hB = (float*)p_hB;
    __nv_bfloat16* bhi = (__nv_bfloat16*)p_bhi;
    __nv_bfloat16* blo = (__nv_bfloat16*)p_blo;
    float* ale = (float*)p_ale;
    float* wasp = (float*)p_was;
    float* wadp = (float*)p_wad;
    float* al0s = (float*)p_alsrc;
    float* al0d = (float*)p_aldst;

    const int SMEM_BYTES = 40960;
    cudaFuncSetAttribute((const void*)k_hgemm<512, 128>,
                         cudaFuncAttributeMaxDynamicSharedMemorySize, SMEM_BYTES);
    cudaFuncSetAttribute((const void*)k_hgemm<512, 256>,
                         cudaFuncAttributeMaxDynamicSharedMemorySize, SMEM_BYTES);
    cudaFuncSetAttribute((const void*)k_hgemm<1024, 128>,
                         cudaFuncAttributeMaxDynamicSharedMemorySize, SMEM_BYTES);

    cudaMemsetAsync(p_zmem, 0, 680000);

    k_big<<<1249, 256>>>(dst, degp,
                         W[0], We[0], As[0], Ad[0], Ae[0],
                         W[1], We[1], As[1], Ad[1], Ae[1],
                         W[2], We[2], As[2], Ad[2], Ae[2],
                         bhi, blo);
    k_scan<<<1, 1024>>>(degp);
    k_alale<<<625 + 1250 + 2500, 256>>>(dst, x, wasp, wadp, eattr);

    const size_t boff[3] = {0, 65536, 196608};
    const int MB = (NN + 63) / 64;   // 157
    const int FB = (NN + 7) / 8;     // 1250

    // layer 0
    k_fsa<128><<<FB, 256>>>(src, x, ale + 0, al0s, al0d, yhi, ylo);
    k_hgemm<512, 128><<<dim3(MB, 2), 256, SMEM_BYTES>>>(
        yhi, ylo, bhi + boff[0], blo + boff[0], Bb[0], hA,
        wasp + 1 * 1024, wadp + 1 * 1024, an + 0 * NNHH, an + 1 * NNHH);
    // layer 1
    k_fsa<128><<<FB, 256>>>(src, hA, ale + 4,
                            an + 0 * NNHH, an + 1 * NNHH, yhi, ylo);
    k_hgemm<512, 256><<<dim3(MB, 4), 256, SMEM_BYTES>>>(
        yhi, ylo, bhi + boff[1], blo + boff[1], Bb[1], hB,
        wasp + 2 * 1024, wadp + 2 * 1024, an + 2 * NNHH, an + 3 * NNHH);
    // layer 2
    k_fsa<256><<<FB, 256>>>(src, hB, ale + 8,
                            an + 2 * NNHH, an + 3 * NNHH, yhi, ylo);
    k_hgemm<1024, 128><<<dim3(MB, 2), 256, SMEM_BYTES>>>(
        yhi, ylo, bhi + boff[2], blo + boff[2], Bb[2], hA,
        nullptr, nullptr, nullptr, nullptr);

    k_pool2<<<GG, 128>>>(batch, hA, out);
}